// round 3
// baseline (speedup 1.0000x reference)
#include <cuda_runtime.h>

// FastFood layer, D=1024, R=4, M=16384 rows. One warp per row.
//
// Layouts within a warp (lane l, register k):
//   A: idx = k*32 + l      B: idx = l*32 + k
// FWHT_1024 = reg-butterflies (5 stages) + lane<->reg transpose + reg-butterflies (5 stages).
// Transpose = 5-stage pairwise exchange: 16 shfl per stage (80 shfl total).
// Gather runs in layout B (thread-contiguous j -> int4/float4 table loads);
// FWHT#2 transposes back to layout A for a coalesced store.

#define FF_D 1024
#define FF_R 4
#define WARPS_PER_BLOCK 8
#define THREADS (WARPS_PER_BLOCK * 32)

// B is +/-1: g_bpack[r*32 + l] bit k = signbit(B[r][k*32+l]).  S prescaled by 1/32.
__device__ unsigned int g_bpack[FF_R * 32];
__device__ float        g_spre[FF_R * FF_D];

__global__ void prep_kernel(const float* __restrict__ B, const float* __restrict__ S) {
    int t = threadIdx.x;                  // 256 threads
    if (t < FF_R * 32) {
        int r = t >> 5, l = t & 31;
        unsigned int m = 0;
        #pragma unroll
        for (int k = 0; k < 32; k++)
            m |= (__float_as_uint(B[r * FF_D + k * 32 + l]) >> 31) << k;
        g_bpack[t] = m;
    }
    for (int i = t; i < FF_R * FF_D; i += 256)
        g_spre[i] = S[i] * 0.03125f;      // 1/sqrt(1024)
}

__device__ __forceinline__ void fwht_reg(float v[32]) {
    // H32 over the 5 register-index bits (fma pipe only)
    #pragma unroll
    for (int m = 1; m <= 16; m <<= 1) {
        #pragma unroll
        for (int k = 0; k < 32; k++) {
            if ((k & m) == 0) {
                float a = v[k], b = v[k | m];
                v[k]     = a + b;
                v[k | m] = a - b;
            }
        }
    }
}

// Swap lane bits with register bits: layout A <-> layout B. 80 shfls.
__device__ __forceinline__ void wtranspose(float v[32], int lane) {
    #pragma unroll
    for (int m = 1; m <= 16; m <<= 1) {
        const bool up = (lane & m) != 0;
        #pragma unroll
        for (int k0 = 0; k0 < 32; k0++) {
            if (k0 & m) continue;          // 16 pairs (k0, k0|m)
            const int k1 = k0 | m;
            float s = up ? v[k0] : v[k1];
            float w = __shfl_xor_sync(0xffffffffu, s, m);
            if (up) v[k0] = w; else v[k1] = w;
        }
    }
}

__global__ __launch_bounds__(THREADS)
void fastfood_kernel(const float* __restrict__ x,
                     const float* __restrict__ G,
                     const int*   __restrict__ P,
                     float* __restrict__ out, int M)
{
    __shared__ float sc[WARPS_PER_BLOCK][32 * 33];   // stride-33 padded scratch
    const int warp = threadIdx.x >> 5;
    const int lane = threadIdx.x & 31;
    const int row  = blockIdx.x * WARPS_PER_BLOCK + warp;
    if (row >= M) return;
    float* sm = sc[warp];
    const float* xr = x + (size_t)row * FF_D;

    #pragma unroll 1
    for (int r = 0; r < FF_R; r++) {
        // ---- v = x * B[r] (sign-bit xor), layout A ----
        const unsigned int bp = g_bpack[r * 32 + lane];
        float v[32];
        #pragma unroll
        for (int k = 0; k < 32; k++)
            v[k] = __uint_as_float(__float_as_uint(xr[k * 32 + lane]) ^
                                   ((bp << (31 - k)) & 0x80000000u));

        // ---- FWHT #1: bits 5-9, transpose, bits 0-4 (A -> B) ----
        fwht_reg(v);
        wtranspose(v, lane);
        fwht_reg(v);

        // ---- permutation gather + G (layout B: j = lane*32 + k) ----
        __syncwarp();                       // prior gather reads done before overwrite
        #pragma unroll
        for (int k = 0; k < 32; k++) sm[lane * 33 + k] = v[k];   // sm[pad(j)] = h1[j], CF
        __syncwarp();
        const int4*   P4 = reinterpret_cast<const int4*>  (P + r * FF_D + lane * 32);
        const float4* G4 = reinterpret_cast<const float4*>(G + r * FF_D + lane * 32);
        #pragma unroll
        for (int q = 0; q < 8; q++) {
            int4   p4 = P4[q];
            float4 g4 = G4[q];
            v[4*q+0] = sm[p4.x + (p4.x >> 5)] * g4.x;
            v[4*q+1] = sm[p4.y + (p4.y >> 5)] * g4.y;
            v[4*q+2] = sm[p4.z + (p4.z >> 5)] * g4.z;
            v[4*q+3] = sm[p4.w + (p4.w >> 5)] * g4.w;
        }

        // ---- FWHT #2: bits 0-4, transpose, bits 5-9 (B -> A) ----
        fwht_reg(v);
        wtranspose(v, lane);
        fwht_reg(v);

        // ---- scale (prescaled S) + coalesced store, layout A ----
        const float* Sp = g_spre + r * FF_D;
        float* o = out + (size_t)row * (FF_R * FF_D) + r * FF_D;
        #pragma unroll
        for (int k = 0; k < 32; k++) {
            int j = k * 32 + lane;
            o[j] = v[k] * Sp[j];
        }
    }
}

extern "C" void kernel_launch(void* const* d_in, const int* in_sizes, int n_in,
                              void* d_out, int out_size) {
    const float* x = (const float*)d_in[0];   // (4,512,8,1024) fp32
    const float* B = (const float*)d_in[1];   // (4,1024) fp32
    const float* G = (const float*)d_in[2];   // (4,1024) fp32
    const float* S = (const float*)d_in[3];   // (4,1024) fp32
    const int*   P = (const int*)  d_in[4];   // (4,1024) int32
    float* out = (float*)d_out;

    const int M = in_sizes[0] / FF_D;         // 16384 rows
    prep_kernel<<<1, 256>>>(B, S);
    const int blocks = (M + WARPS_PER_BLOCK - 1) / WARPS_PER_BLOCK;
    fastfood_kernel<<<blocks, THREADS>>>(x, G, P, out, M);
}

// round 4
// speedup vs baseline: 1.3800x; 1.3800x over previous
#include <cuda_runtime.h>

// FastFood layer, D=1024, R=4, M=16384 rows. One warp per row.
//
// Layouts within a warp (lane l, register k):
//   A: idx = k*32 + l      B: idx = l*32 + k
// FWHT_1024 = reg-butterflies (bits 5-9 or 0-4) + lane<->reg exchange transpose.
// Transpose = 5 stages x 16 pairwise exchanges = 80 shfl (vs 160 for shfl-butterfly).
// The permutation gather runs in layout B; P and G are PRE-TRANSPOSED by the prep
// kernel so all gather-phase table loads stay warp-coalesced (R3's mistake).

#define FF_D 1024
#define FF_R 4
#define WARPS_PER_BLOCK 8
#define THREADS (WARPS_PER_BLOCK * 32)

__device__ unsigned int g_bpack[FF_R * 32];      // bit k = signbit(B[r][k*32+l])
__device__ int          g_pt[FF_R * FF_D];       // Pt[r][k*32+l] = pad(P[r][l*32+k])
__device__ float        g_gt[FF_R * FF_D];       // Gt[r][k*32+l] = G[r][l*32+k]
__device__ float        g_spre[FF_R * FF_D];     // S / 32

__global__ void prep_kernel(const float* __restrict__ B, const float* __restrict__ G,
                            const float* __restrict__ S, const int* __restrict__ P) {
    int t = blockIdx.x * blockDim.x + threadIdx.x;
    int stride = gridDim.x * blockDim.x;
    if (t < FF_R * 32) {
        int r = t >> 5, l = t & 31;
        unsigned int m = 0;
        #pragma unroll
        for (int k = 0; k < 32; k++)
            m |= (__float_as_uint(B[r * FF_D + k * 32 + l]) >> 31) << k;
        g_bpack[t] = m;
    }
    for (int i = t; i < FF_R * FF_D; i += stride) {
        int r = i >> 10, j = i & 1023;           // j = k*32 + l (dest, layout-B coalesced)
        int k = j >> 5, l = j & 31;
        int src = r * FF_D + l * 32 + k;         // source index in original layout
        int p = P[src];
        g_pt[i] = p + (p >> 5);                  // pad() folded in
        g_gt[i] = G[src];
        g_spre[i] = S[i] * 0.03125f;             // 1/sqrt(1024), natural order
    }
}

__device__ __forceinline__ void fwht_reg(float v[32]) {
    // H32 over the 5 register-index bits (fma pipe, no cross-lane traffic)
    #pragma unroll
    for (int m = 1; m <= 16; m <<= 1) {
        #pragma unroll
        for (int k = 0; k < 32; k++) {
            if ((k & m) == 0) {
                float a = v[k], b = v[k | m];
                v[k]     = a + b;
                v[k | m] = a - b;
            }
        }
    }
}

// Swap lane bits with register bits (layout A <-> B). 80 shfl + SELs.
__device__ __forceinline__ void wtranspose(float v[32], int lane) {
    #pragma unroll
    for (int m = 1; m <= 16; m <<= 1) {
        const bool up = (lane & m) != 0;
        #pragma unroll
        for (int k0 = 0; k0 < 32; k0++) {
            if (k0 & m) continue;
            const int k1 = k0 | m;
            float t = up ? v[k0] : v[k1];
            float w = __shfl_xor_sync(0xffffffffu, t, m);
            if (up) v[k0] = w; else v[k1] = w;
        }
    }
}

__global__ __launch_bounds__(THREADS, 3)
void fastfood_kernel(const float* __restrict__ x,
                     float* __restrict__ out, int M)
{
    __shared__ float sc[WARPS_PER_BLOCK][32 * 33];   // stride-33 padded scratch
    const int warp = threadIdx.x >> 5;
    const int lane = threadIdx.x & 31;
    const int row  = blockIdx.x * WARPS_PER_BLOCK + warp;
    if (row >= M) return;
    float* sm = sc[warp];
    const float* xr = x + (size_t)row * FF_D;

    #pragma unroll 1
    for (int r = 0; r < FF_R; r++) {
        // ---- v = x * B[r] (sign-bit xor), layout A ----
        const unsigned int bp = g_bpack[r * 32 + lane];
        float v[32];
        #pragma unroll
        for (int k = 0; k < 32; k++)
            v[k] = __uint_as_float(__float_as_uint(xr[k * 32 + lane]) ^
                                   ((bp << (31 - k)) & 0x80000000u));

        // ---- FWHT #1: bits 5-9 (A), transpose, bits 0-4 (B) ----
        fwht_reg(v);
        wtranspose(v, lane);
        fwht_reg(v);

        // ---- permutation gather + G (layout B, pre-transposed coalesced tables) ----
        __syncwarp();                               // prior r's gather reads done
        #pragma unroll
        for (int k = 0; k < 32; k++) sm[lane * 33 + k] = v[k];   // sm[pad(l*32+k)], CF
        __syncwarp();
        const int*   Pt = g_pt + r * FF_D;
        const float* Gt = g_gt + r * FF_D;
        #pragma unroll
        for (int k = 0; k < 32; k++) {
            int j = k * 32 + lane;                  // coalesced table index
            v[k] = sm[Pt[j]] * Gt[j];               // Pt already pad()-folded
        }

        // ---- FWHT #2: bits 0-4 (B), transpose, bits 5-9 (A) ----
        fwht_reg(v);
        wtranspose(v, lane);
        fwht_reg(v);

        // ---- scale (prescaled S) + coalesced store, layout A ----
        const float* Sp = g_spre + r * FF_D;
        float* o = out + (size_t)row * (FF_R * FF_D) + r * FF_D;
        #pragma unroll
        for (int k = 0; k < 32; k++) {
            int j = k * 32 + lane;
            o[j] = v[k] * Sp[j];
        }
    }
}

extern "C" void kernel_launch(void* const* d_in, const int* in_sizes, int n_in,
                              void* d_out, int out_size) {
    const float* x = (const float*)d_in[0];   // (4,512,8,1024) fp32
    const float* B = (const float*)d_in[1];   // (4,1024) fp32
    const float* G = (const float*)d_in[2];   // (4,1024) fp32
    const float* S = (const float*)d_in[3];   // (4,1024) fp32
    const int*   P = (const int*)  d_in[4];   // (4,1024) int32
    float* out = (float*)d_out;

    const int M = in_sizes[0] / FF_D;         // 16384 rows
    prep_kernel<<<32, 256>>>(B, G, S, P);
    const int blocks = (M + WARPS_PER_BLOCK - 1) / WARPS_PER_BLOCK;
    fastfood_kernel<<<blocks, THREADS>>>(x, out, M);
}

// round 5
// speedup vs baseline: 2.2948x; 1.6629x over previous
#include <cuda_runtime.h>

// FastFood layer, D=1024, R=4, M=16384 rows. One warp per row. ZERO shuffles.
//
// Layouts within a warp (lane l, register k):
//   A: idx = k*32 + l      B: idx = l*32 + k
// FWHT_1024 = reg-butterflies over one 5-bit group + padded-smem transpose +
// reg-butterflies over the other group. All smem traffic conflict-free via
// stride-33 rows: slot(idx) = idx + (idx>>5).
// Permutation gather runs in layout B with PRE-TRANSPOSED (coalesced) P/G tables,
// P and G fused into one int2 so the gather does a single LDG.64 per element.

#define FF_D 1024
#define FF_R 4
#define WPB 8
#define THREADS (WPB * 32)

__device__ unsigned int g_bpack[FF_R * 32];   // bit k = signbit(B[r][k*32+l])
__device__ int2         g_pg[FF_R * FF_D];    // [r][k*32+l] = { pad(P[r][l*32+k]), bits(G[r][l*32+k]) }
__device__ float        g_spre[FF_R * FF_D];  // S / 32, natural order

__global__ void prep_kernel(const float* __restrict__ B, const float* __restrict__ G,
                            const float* __restrict__ S, const int* __restrict__ P) {
    int t = blockIdx.x * blockDim.x + threadIdx.x;
    int stride = gridDim.x * blockDim.x;
    if (t < FF_R * 32) {
        int r = t >> 5, l = t & 31;
        unsigned int m = 0;
        #pragma unroll
        for (int k = 0; k < 32; k++)
            m |= (__float_as_uint(B[r * FF_D + k * 32 + l]) >> 31) << k;
        g_bpack[t] = m;
    }
    for (int i = t; i < FF_R * FF_D; i += stride) {
        int r = i >> 10, j = i & 1023;          // dest j = k*32 + l (coalesced in layout B)
        int k = j >> 5, l = j & 31;
        int src = r * FF_D + l * 32 + k;
        int p = P[src];
        g_pg[i] = make_int2(p + (p >> 5), __float_as_int(G[src]));
        g_spre[i] = S[i] * 0.03125f;            // 1/sqrt(1024)
    }
}

__device__ __forceinline__ void fwht_reg(float v[32]) {
    // H32 over the 5 register-index bits (fma pipe only, 16-wide ILP per stage)
    #pragma unroll
    for (int m = 1; m <= 16; m <<= 1) {
        #pragma unroll
        for (int k = 0; k < 32; k++) {
            if ((k & m) == 0) {
                float a = v[k], b = v[k | m];
                v[k]     = a + b;
                v[k | m] = a - b;
            }
        }
    }
}

__global__ __launch_bounds__(THREADS, 4)
void fastfood_kernel(const float* __restrict__ x,
                     float* __restrict__ out, int M)
{
    __shared__ float sc[WPB][32 * 33];          // stride-33 padded, per-warp private
    const int warp = threadIdx.x >> 5;
    const int lane = threadIdx.x & 31;
    const int row  = blockIdx.x * WPB + warp;
    if (row >= M) return;
    float* sm = sc[warp];
    const float* xr = x + (size_t)row * FF_D;

    #pragma unroll 1
    for (int r = 0; r < FF_R; r++) {
        // ---- v = x * B[r] (sign-bit xor), layout A ----
        const unsigned int bp = g_bpack[r * 32 + lane];
        float v[32];
        #pragma unroll
        for (int k = 0; k < 32; k++)
            v[k] = __uint_as_float(__float_as_uint(__ldg(&xr[k * 32 + lane])) ^
                                   ((bp << (31 - k)) & 0x80000000u));

        // ---- FWHT #1: high bits (A) ----
        fwht_reg(v);
        // transpose A -> B  (STS writes column `lane`; prev-iter LDS#3 read column `lane`
        // by this same thread, so no sync needed at loop top)
        #pragma unroll
        for (int k = 0; k < 32; k++) sm[k * 33 + lane] = v[k];
        __syncwarp();
        #pragma unroll
        for (int k = 0; k < 32; k++) v[k] = sm[lane * 33 + k];      // row `lane` -> layout B
        // ---- FWHT #1: low bits (B) -> h1 ----
        fwht_reg(v);

        // ---- gather: h1 to smem (this thread re-writes its own row: no sync) ----
        #pragma unroll
        for (int k = 0; k < 32; k++) sm[lane * 33 + k] = v[k];
        __syncwarp();
        const int2* PG = g_pg + r * FF_D;
        #pragma unroll
        for (int k = 0; k < 32; k++) {
            int2 pg = __ldg(&PG[k * 32 + lane]);                     // coalesced LDG.64
            v[k] = sm[pg.x] * __int_as_float(pg.y);
        }
        __syncwarp();                                                // gathers done before overwrite

        // ---- FWHT #2: low bits (B) ----
        fwht_reg(v);
        // transpose B -> A (this thread re-writes its own row: no extra sync needed
        // beyond the one above)
        #pragma unroll
        for (int k = 0; k < 32; k++) sm[lane * 33 + k] = v[k];
        __syncwarp();
        #pragma unroll
        for (int k = 0; k < 32; k++) v[k] = sm[k * 33 + lane];      // column `lane` -> layout A
        // ---- FWHT #2: high bits (A) ----
        fwht_reg(v);

        // ---- scale (prescaled S) + coalesced store ----
        const float* Sp = g_spre + r * FF_D;
        float* o = out + (size_t)row * (FF_R * FF_D) + r * FF_D;
        #pragma unroll
        for (int k = 0; k < 32; k++) {
            int j = k * 32 + lane;
            o[j] = v[k] * __ldg(&Sp[j]);
        }
    }
}

extern "C" void kernel_launch(void* const* d_in, const int* in_sizes, int n_in,
                              void* d_out, int out_size) {
    const float* x = (const float*)d_in[0];   // (4,512,8,1024) fp32
    const float* B = (const float*)d_in[1];   // (4,1024) fp32
    const float* G = (const float*)d_in[2];   // (4,1024) fp32
    const float* S = (const float*)d_in[3];   // (4,1024) fp32
    const int*   P = (const int*)  d_in[4];   // (4,1024) int32
    float* out = (float*)d_out;

    const int M = in_sizes[0] / FF_D;         // 16384 rows
    prep_kernel<<<32, 256>>>(B, G, S, P);
    const int blocks = (M + WPB - 1) / WPB;
    fastfood_kernel<<<blocks, THREADS>>>(x, out, M);
}

// round 6
// speedup vs baseline: 2.3860x; 1.0397x over previous
#include <cuda_runtime.h>

// FastFood layer, D=1024, R=4, M=16384 rows. One warp per row. Zero shuffles.
//
// Layouts within a warp (lane l, register k):
//   A: idx = k*32 + l      B: idx = l*32 + k
// FWHT_1024 = reg-butterflies over one 5-bit group + padded-smem transpose +
// reg-butterflies over the other group.
// Padding: stride 36 floats per 32-element row -> 16B-aligned rows, so the
// row side of every smem sweep is float4 (LDS.128/STS.128), all conflict-free.
// slot(idx) = idx + (idx>>5)*4.
// Permutation gather in layout B with pre-transposed tables; P+G packed as int4
// pairs so table loads are LDG.128.

#define FF_D 1024
#define FF_R 4
#define WPB 8
#define THREADS (WPB * 32)
#define ROWSTRIDE 36

__device__ unsigned int g_bpack[FF_R * 32];   // bit k = signbit(B[r][k*32+l])
__device__ int4         g_pg4[FF_R * 512];    // [r][q*32+l] = {slot(P[j0]),G[j0],slot(P[j1]),G[j1]}, j=l*32+2q(+1)
__device__ float        g_spre[FF_R * FF_D];  // S / 32, natural order

__global__ void prep_kernel(const float* __restrict__ B, const float* __restrict__ G,
                            const float* __restrict__ S, const int* __restrict__ P) {
    int t = blockIdx.x * blockDim.x + threadIdx.x;
    int stride = gridDim.x * blockDim.x;
    if (t < FF_R * 32) {
        int r = t >> 5, l = t & 31;
        unsigned int m = 0;
        #pragma unroll
        for (int k = 0; k < 32; k++)
            m |= (__float_as_uint(B[r * FF_D + k * 32 + l]) >> 31) << k;
        g_bpack[t] = m;
    }
    for (int i = t; i < FF_R * 512; i += stride) {
        int r = i >> 9, rem = i & 511;
        int q = rem >> 5, l = rem & 31;
        int j0 = r * FF_D + l * 32 + 2 * q;
        int p0 = P[j0], p1 = P[j0 + 1];
        g_pg4[i] = make_int4(p0 + ((p0 >> 5) << 2), __float_as_int(G[j0]),
                             p1 + ((p1 >> 5) << 2), __float_as_int(G[j0 + 1]));
    }
    for (int i = t; i < FF_R * FF_D; i += stride)
        g_spre[i] = S[i] * 0.03125f;          // 1/sqrt(1024)
}

__device__ __forceinline__ void fwht_reg(float v[32]) {
    // H32 over the 5 register-index bits (fma pipe only, 16-wide ILP per stage)
    #pragma unroll
    for (int m = 1; m <= 16; m <<= 1) {
        #pragma unroll
        for (int k = 0; k < 32; k++) {
            if ((k & m) == 0) {
                float a = v[k], b = v[k | m];
                v[k]     = a + b;
                v[k | m] = a - b;
            }
        }
    }
}

__global__ __launch_bounds__(THREADS, 4)
void fastfood_kernel(const float* __restrict__ x,
                     float* __restrict__ out, int M)
{
    __shared__ float sc[WPB][32 * ROWSTRIDE];     // 4608 B per warp, private
    const int warp = threadIdx.x >> 5;
    const int lane = threadIdx.x & 31;
    const int row  = blockIdx.x * WPB + warp;
    if (row >= M) return;
    float* sm = sc[warp];
    float4* myrow = reinterpret_cast<float4*>(sm + lane * ROWSTRIDE);  // 16B aligned
    const float* xr = x + (size_t)row * FF_D;

    #pragma unroll 1
    for (int r = 0; r < FF_R; r++) {
        // ---- v = x * B[r] (sign-bit xor), layout A ----
        const unsigned int bp = g_bpack[r * 32 + lane];
        float v[32];
        #pragma unroll
        for (int k = 0; k < 32; k++)
            v[k] = __uint_as_float(__float_as_uint(__ldg(&xr[k * 32 + lane])) ^
                                   ((bp << (31 - k)) & 0x80000000u));

        // ---- FWHT #1: high bits (A) ----
        fwht_reg(v);
        // transpose A -> B: scalar column writes, float4 row reads.
        // (prev iter's last reads were this thread's own column: no sync at top)
        #pragma unroll
        for (int k = 0; k < 32; k++) sm[k * ROWSTRIDE + lane] = v[k];
        __syncwarp();
        #pragma unroll
        for (int q = 0; q < 8; q++) {
            float4 t = myrow[q];
            v[4*q+0] = t.x; v[4*q+1] = t.y; v[4*q+2] = t.z; v[4*q+3] = t.w;
        }
        // ---- FWHT #1: low bits (B) -> h1 ----
        fwht_reg(v);

        // ---- gather: h1 to smem rows (own row rewrite: no sync), STS.128 ----
        #pragma unroll
        for (int q = 0; q < 8; q++)
            myrow[q] = make_float4(v[4*q+0], v[4*q+1], v[4*q+2], v[4*q+3]);
        __syncwarp();
        const int4* PG = g_pg4 + r * 512;
        #pragma unroll
        for (int q = 0; q < 16; q++) {
            int4 pg = __ldg(&PG[q * 32 + lane]);              // LDG.128 coalesced
            v[2*q+0] = sm[pg.x] * __int_as_float(pg.y);
            v[2*q+1] = sm[pg.z] * __int_as_float(pg.w);
        }
        __syncwarp();                                          // gathers done before overwrite

        // ---- FWHT #2: low bits (B) ----
        fwht_reg(v);
        // transpose B -> A: float4 row writes, scalar column reads
        #pragma unroll
        for (int q = 0; q < 8; q++)
            myrow[q] = make_float4(v[4*q+0], v[4*q+1], v[4*q+2], v[4*q+3]);
        __syncwarp();
        #pragma unroll
        for (int k = 0; k < 32; k++) v[k] = sm[k * ROWSTRIDE + lane];
        // ---- FWHT #2: high bits (A) ----
        fwht_reg(v);

        // ---- scale (prescaled S) + coalesced store ----
        const float* Sp = g_spre + r * FF_D;
        float* o = out + (size_t)row * (FF_R * FF_D) + r * FF_D;
        #pragma unroll
        for (int k = 0; k < 32; k++) {
            int j = k * 32 + lane;
            o[j] = v[k] * __ldg(&Sp[j]);
        }
    }
}

extern "C" void kernel_launch(void* const* d_in, const int* in_sizes, int n_in,
                              void* d_out, int out_size) {
    const float* x = (const float*)d_in[0];   // (4,512,8,1024) fp32
    const float* B = (const float*)d_in[1];   // (4,1024) fp32
    const float* G = (const float*)d_in[2];   // (4,1024) fp32
    const float* S = (const float*)d_in[3];   // (4,1024) fp32
    const int*   P = (const int*)  d_in[4];   // (4,1024) int32
    float* out = (float*)d_out;

    const int M = in_sizes[0] / FF_D;         // 16384 rows
    prep_kernel<<<32, 256>>>(B, G, S, P);
    const int blocks = (M + WPB - 1) / WPB;
    fastfood_kernel<<<blocks, THREADS>>>(x, out, M);
}

// round 8
// speedup vs baseline: 2.8392x; 1.1900x over previous
#include <cuda_runtime.h>
#include <cuda_fp16.h>

// FastFood layer, D=1024, R=4, M=16384 rows. One warp per row. Zero shuffles.
// Intermediates round-trip through a per-warp fp16 smem image (butterflies in fp32 regs).
//
// Layouts within a warp (lane l, register k):
//   A: idx = k*32 + l      B: idx = l*32 + k
// smem image: 32 rows x 36 halves (72B rows, 8B-aligned). slot16(i) = (i>>5)*36 + (i&31).
// Row accesses = half4 (uint2). Column accesses = scalar STS.16/LDS.U16.
// PG table: one u32 per element = (slot16(P[j])<<16) | half_bits(G[j]), int4 = 4 elements.

#define FF_D 1024
#define FF_R 4
#define WPB 8
#define THREADS (WPB * 32)
#define RS 36   // halves per smem row

__device__ unsigned int g_bpack[FF_R * 32];   // bit k = signbit(B[r][k*32+l])
__device__ int4         g_pg4[FF_R * 256];    // [r][q*32+l] = entries for j = l*32+4q+{0..3}
__device__ float        g_spre[FF_R * FF_D];  // S / 32, natural order

__global__ void prep_kernel(const float* __restrict__ B, const float* __restrict__ G,
                            const float* __restrict__ S, const int* __restrict__ P) {
    int t = blockIdx.x * blockDim.x + threadIdx.x;
    int stride = gridDim.x * blockDim.x;
    if (t < FF_R * 32) {
        int r = t >> 5, l = t & 31;
        unsigned int m = 0;
        #pragma unroll
        for (int k = 0; k < 32; k++)
            m |= (__float_as_uint(B[r * FF_D + k * 32 + l]) >> 31) << k;
        g_bpack[t] = m;
    }
    for (int i = t; i < FF_R * 256; i += stride) {
        int r = i >> 8, rem = i & 255;
        int q = rem >> 5, l = rem & 31;
        int j = r * FF_D + l * 32 + 4 * q;       // 4 consecutive dest elements
        unsigned int e[4];
        #pragma unroll
        for (int u = 0; u < 4; u++) {
            int p = P[j + u];
            unsigned int slot = (unsigned int)((p >> 5) * RS + (p & 31));
            unsigned short gh = __half_as_ushort(__float2half_rn(G[j + u]));
            e[u] = (slot << 16) | (unsigned int)gh;
        }
        g_pg4[i] = make_int4((int)e[0], (int)e[1], (int)e[2], (int)e[3]);
    }
    for (int i = t; i < FF_R * FF_D; i += stride)
        g_spre[i] = S[i] * 0.03125f;             // 1/sqrt(1024)
}

__device__ __forceinline__ void fwht_reg(float v[32]) {
    #pragma unroll
    for (int m = 1; m <= 16; m <<= 1) {
        #pragma unroll
        for (int k = 0; k < 32; k++) {
            if ((k & m) == 0) {
                float a = v[k], b = v[k | m];
                v[k]     = a + b;
                v[k | m] = a - b;
            }
        }
    }
}

__device__ __forceinline__ unsigned int pack2(float a, float b) {
    __half2 h = __floats2half2_rn(a, b);
    return *reinterpret_cast<unsigned int*>(&h);
}
__device__ __forceinline__ float2 unpack2(unsigned int u) {
    __half2 h = *reinterpret_cast<__half2*>(&u);
    return __half22float2(h);
}

__global__ __launch_bounds__(THREADS, 4)
void fastfood_kernel(const float* __restrict__ x,
                     float* __restrict__ out, int M)
{
    __shared__ __half sc[WPB][32 * RS];           // 2304 B per warp
    const int warp = threadIdx.x >> 5;
    const int lane = threadIdx.x & 31;
    const int row  = blockIdx.x * WPB + warp;
    if (row >= M) return;
    __half* smh = sc[warp];
    uint2* myrow = reinterpret_cast<uint2*>(smh + lane * RS);   // 72B base: 8B aligned
    const float* xr = x + (size_t)row * FF_D;

    #pragma unroll 1
    for (int r = 0; r < FF_R; r++) {
        // ---- v = x * B[r] (sign-bit xor), layout A, fp32 ----
        const unsigned int bp = g_bpack[r * 32 + lane];
        float v[32];
        #pragma unroll
        for (int k = 0; k < 32; k++)
            v[k] = __uint_as_float(__float_as_uint(__ldg(&xr[k * 32 + lane])) ^
                                   ((bp << (31 - k)) & 0x80000000u));

        // ---- FWHT #1: high bits (A) ----
        fwht_reg(v);
        // transpose A -> B: scalar fp16 column writes, half4 row reads
        #pragma unroll
        for (int k = 0; k < 32; k++) smh[k * RS + lane] = __float2half_rn(v[k]);
        __syncwarp();
        #pragma unroll
        for (int q = 0; q < 8; q++) {
            uint2 d = myrow[q];
            float2 a = unpack2(d.x), b = unpack2(d.y);
            v[4*q+0] = a.x; v[4*q+1] = a.y; v[4*q+2] = b.x; v[4*q+3] = b.y;
        }
        // ---- FWHT #1: low bits (B) -> h1 ----
        fwht_reg(v);

        // ---- gather image: h1 to own row (half4), then permuted reads ----
        #pragma unroll
        for (int q = 0; q < 8; q++)
            myrow[q] = make_uint2(pack2(v[4*q+0], v[4*q+1]), pack2(v[4*q+2], v[4*q+3]));
        __syncwarp();
        const int4* PG = g_pg4 + r * 256;
        #pragma unroll
        for (int q = 0; q < 8; q++) {
            int4 pg = __ldg(&PG[q * 32 + lane]);               // LDG.128: 4 elements
            unsigned int e0 = (unsigned int)pg.x, e1 = (unsigned int)pg.y;
            unsigned int e2 = (unsigned int)pg.z, e3 = (unsigned int)pg.w;
            v[4*q+0] = __half2float(smh[e0 >> 16]) * __half2float(__ushort_as_half((unsigned short)(e0 & 0xffffu)));
            v[4*q+1] = __half2float(smh[e1 >> 16]) * __half2float(__ushort_as_half((unsigned short)(e1 & 0xffffu)));
            v[4*q+2] = __half2float(smh[e2 >> 16]) * __half2float(__ushort_as_half((unsigned short)(e2 & 0xffffu)));
            v[4*q+3] = __half2float(smh[e3 >> 16]) * __half2float(__ushort_as_half((unsigned short)(e3 & 0xffffu)));
        }
        __syncwarp();                                           // all gathers done before overwrite

        // ---- FWHT #2: low bits (B) ----
        fwht_reg(v);
        // transpose B -> A: half4 row writes, scalar fp16 column reads
        #pragma unroll
        for (int q = 0; q < 8; q++)
            myrow[q] = make_uint2(pack2(v[4*q+0], v[4*q+1]), pack2(v[4*q+2], v[4*q+3]));
        __syncwarp();
        #pragma unroll
        for (int k = 0; k < 32; k++) v[k] = __half2float(smh[k * RS + lane]);
        // ---- FWHT #2: high bits (A) ----
        fwht_reg(v);

        // ---- scale (prescaled fp32 S) + coalesced fp32 store ----
        const float* Sp = g_spre + r * FF_D;
        float* o = out + (size_t)row * (FF_R * FF_D) + r * FF_D;
        #pragma unroll
        for (int k = 0; k < 32; k++) {
            int j = k * 32 + lane;
            o[j] = v[k] * __ldg(&Sp[j]);
        }
    }
}

extern "C" void kernel_launch(void* const* d_in, const int* in_sizes, int n_in,
                              void* d_out, int out_size) {
    const float* x = (const float*)d_in[0];   // (4,512,8,1024) fp32
    const float* B = (const float*)d_in[1];   // (4,1024) fp32
    const float* G = (const float*)d_in[2];   // (4,1024) fp32
    const float* S = (const float*)d_in[3];   // (4,1024) fp32
    const int*   P = (const int*)  d_in[4];   // (4,1024) int32
    float* out = (float*)d_out;

    const int M = in_sizes[0] / FF_D;         // 16384 rows
    prep_kernel<<<32, 256>>>(B, G, S, P);
    const int blocks = (M + WPB - 1) / WPB;
    fastfood_kernel<<<blocks, THREADS>>>(x, out, M);
}